// round 2
// baseline (speedup 1.0000x reference)
#include <cuda_runtime.h>
#include <cuda_bf16.h>

#define BATCH 8
#define NTOK  1024
#define EDIM  1024
#define NH    16
#define HDIM  64
#define BHN   (BATCH*NH*NTOK)   // 131072 rows of 64

// Scratch (allocation-free requirement -> __device__ globals)
__device__ float g_q[BATCH*NH*NTOK*HDIM];   // [B,H,N,hd]
__device__ float g_k[BATCH*NH*NTOK*HDIM];
__device__ float g_v[BATCH*NH*NTOK*HDIM];
__device__ float g_o[BATCH*NTOK*EDIM];      // [B,N,D] attention output
__device__ unsigned char g_mask[NTOK*NTOK]; // canonicalized boolean mask
__device__ int g_mmode;                     // 0=uint8, 1=int32, 2=float32

// ---------------------------------------------------------------------------
// Mask dtype detection: the reference emits a bool [N,N]; the harness widens it
// to an unknown dtype. Scan the first 262144 words (= min possible buffer size
// if it were 1 byte/elem, so never OOB). all words in {0,1} -> int32;
// all in {0, 0x3F800000} -> float32; else -> uint8.
// ---------------------------------------------------------------------------
__global__ __launch_bounds__(1024)
void mask_detect_kernel(const unsigned int* __restrict__ m) {
    __shared__ int s_int, s_flt;
    if (threadIdx.x == 0) { s_int = 1; s_flt = 1; }
    __syncthreads();
    int bad_int = 0, bad_flt = 0;
    for (int i = threadIdx.x; i < 262144; i += 1024) {
        unsigned int w = m[i];
        if (w > 1u) bad_int = 1;
        if (w != 0u && w != 0x3F800000u) bad_flt = 1;
    }
    if (bad_int) atomicAnd(&s_int, 0);
    if (bad_flt) atomicAnd(&s_flt, 0);
    __syncthreads();
    if (threadIdx.x == 0)
        g_mmode = s_int ? 1 : (s_flt ? 2 : 0);
}

__global__ __launch_bounds__(256)
void mask_convert_kernel(const void* __restrict__ mraw) {
    int mode = g_mmode;
    int i = blockIdx.x * 256 + threadIdx.x;   // grid covers N*N
    unsigned char v;
    if (mode == 1) {
        v = (unsigned char)(((const int*)mraw)[i] != 0);
    } else if (mode == 2) {
        v = (unsigned char)(((const float*)mraw)[i] != 0.f);
    } else {
        v = (unsigned char)(((const unsigned char*)mraw)[i] != 0);
    }
    g_mask[i] = v;
}

// ---------------------------------------------------------------------------
// GEMM NT: C[m,n] = sum_k A[m,k] * W[n,k].  A: [8192,1024], W: [1024,1024]
// 64x64 tile, BK=16, 256 threads, 4x4 per thread.
// ---------------------------------------------------------------------------

__global__ __launch_bounds__(256)
void gemm_qkv_kernel(const float* __restrict__ x,
                     const float* __restrict__ Wq,
                     const float* __restrict__ Wk,
                     const float* __restrict__ Wv) {
    __shared__ float As[16][68];
    __shared__ float Bs[16][68];

    const float* W   = (blockIdx.z == 0) ? Wq : (blockIdx.z == 1) ? Wk : Wv;
    float*       dst = (blockIdx.z == 0) ? g_q : (blockIdx.z == 1) ? g_k : g_v;

    int tid = threadIdx.x;
    int tx = tid & 15, ty = tid >> 4;
    int m0 = blockIdx.y * 64, n0 = blockIdx.x * 64;
    int lr = tid >> 2, lq = tid & 3;

    float acc[4][4];
#pragma unroll
    for (int i = 0; i < 4; i++)
#pragma unroll
        for (int j = 0; j < 4; j++) acc[i][j] = 0.f;

    for (int k0 = 0; k0 < EDIM; k0 += 16) {
        float4 a = *(const float4*)&x[(size_t)(m0 + lr) * EDIM + k0 + lq * 4];
        As[lq*4+0][lr] = a.x; As[lq*4+1][lr] = a.y;
        As[lq*4+2][lr] = a.z; As[lq*4+3][lr] = a.w;
        float4 b = *(const float4*)&W[(size_t)(n0 + lr) * EDIM + k0 + lq * 4];
        Bs[lq*4+0][lr] = b.x; Bs[lq*4+1][lr] = b.y;
        Bs[lq*4+2][lr] = b.z; Bs[lq*4+3][lr] = b.w;
        __syncthreads();
#pragma unroll
        for (int k = 0; k < 16; k++) {
            float4 av = *(const float4*)&As[k][ty * 4];
            float4 bv = *(const float4*)&Bs[k][tx * 4];
            acc[0][0] += av.x*bv.x; acc[0][1] += av.x*bv.y; acc[0][2] += av.x*bv.z; acc[0][3] += av.x*bv.w;
            acc[1][0] += av.y*bv.x; acc[1][1] += av.y*bv.y; acc[1][2] += av.y*bv.z; acc[1][3] += av.y*bv.w;
            acc[2][0] += av.z*bv.x; acc[2][1] += av.z*bv.y; acc[2][2] += av.z*bv.z; acc[2][3] += av.z*bv.w;
            acc[3][0] += av.w*bv.x; acc[3][1] += av.w*bv.y; acc[3][2] += av.w*bv.z; acc[3][3] += av.w*bv.w;
        }
        __syncthreads();
    }

    // epilogue: transpose into [B,H,N,hd]
#pragma unroll
    for (int i = 0; i < 4; i++) {
        int m  = m0 + ty * 4 + i;
        int b  = m >> 10, nn = m & 1023;
#pragma unroll
        for (int j = 0; j < 4; j++) {
            int n = n0 + tx * 4 + j;
            int h = n >> 6, d = n & 63;
            dst[(((size_t)(b * NH + h) * NTOK) + nn) * HDIM + d] = acc[i][j];
        }
    }
}

__global__ __launch_bounds__(256)
void gemm_out_kernel(const float* __restrict__ Wo, float* __restrict__ out) {
    __shared__ float As[16][68];
    __shared__ float Bs[16][68];

    int tid = threadIdx.x;
    int tx = tid & 15, ty = tid >> 4;
    int m0 = blockIdx.y * 64, n0 = blockIdx.x * 64;
    int lr = tid >> 2, lq = tid & 3;

    float acc[4][4];
#pragma unroll
    for (int i = 0; i < 4; i++)
#pragma unroll
        for (int j = 0; j < 4; j++) acc[i][j] = 0.f;

    for (int k0 = 0; k0 < EDIM; k0 += 16) {
        float4 a = *(const float4*)&g_o[(size_t)(m0 + lr) * EDIM + k0 + lq * 4];
        As[lq*4+0][lr] = a.x; As[lq*4+1][lr] = a.y;
        As[lq*4+2][lr] = a.z; As[lq*4+3][lr] = a.w;
        float4 b = *(const float4*)&Wo[(size_t)(n0 + lr) * EDIM + k0 + lq * 4];
        Bs[lq*4+0][lr] = b.x; Bs[lq*4+1][lr] = b.y;
        Bs[lq*4+2][lr] = b.z; Bs[lq*4+3][lr] = b.w;
        __syncthreads();
#pragma unroll
        for (int k = 0; k < 16; k++) {
            float4 av = *(const float4*)&As[k][ty * 4];
            float4 bv = *(const float4*)&Bs[k][tx * 4];
            acc[0][0] += av.x*bv.x; acc[0][1] += av.x*bv.y; acc[0][2] += av.x*bv.z; acc[0][3] += av.x*bv.w;
            acc[1][0] += av.y*bv.x; acc[1][1] += av.y*bv.y; acc[1][2] += av.y*bv.z; acc[1][3] += av.y*bv.w;
            acc[2][0] += av.z*bv.x; acc[2][1] += av.z*bv.y; acc[2][2] += av.z*bv.z; acc[2][3] += av.z*bv.w;
            acc[3][0] += av.w*bv.x; acc[3][1] += av.w*bv.y; acc[3][2] += av.w*bv.z; acc[3][3] += av.w*bv.w;
        }
        __syncthreads();
    }
#pragma unroll
    for (int i = 0; i < 4; i++) {
        int m = m0 + ty * 4 + i;
#pragma unroll
        for (int j = 0; j < 4; j++) {
            int n = n0 + tx * 4 + j;
            out[(size_t)m * EDIM + n] = acc[i][j];
        }
    }
}

// ---------------------------------------------------------------------------
// QKNorm + gathered 2D RoPE. One warp per (which,b,h,n) row of 64.
// Lane l owns dims l and l+32 -> rotate_half is a local 2-element rotation.
// ---------------------------------------------------------------------------
__global__ __launch_bounds__(256)
void norm_rope_kernel(const float* __restrict__ qg,
                      const float* __restrict__ kgamma,
                      const float* __restrict__ cosb,
                      const float* __restrict__ sinb,
                      const int*   __restrict__ ridx) {
    int warp = (blockIdx.x * blockDim.x + threadIdx.x) >> 5;
    int lane = threadIdx.x & 31;
    int which = (warp >= BHN) ? 1 : 0;
    int r = warp - which * BHN;
    int n = r & (NTOK - 1);

    float* p = (which ? g_k : g_q) + (size_t)r * HDIM;
    const float* gamma = which ? kgamma : qg;

    float x0 = p[lane];
    float x1 = p[lane + 32];
    float ss = x0 * x0 + x1 * x1;
#pragma unroll
    for (int o = 16; o; o >>= 1) ss += __shfl_xor_sync(0xffffffffu, ss, o);
    float rms = rsqrtf(ss * (1.0f / 64.0f) + 1e-6f);
    x0 *= rms * gamma[lane];
    x1 *= rms * gamma[lane + 32];

    int idx = ridx[n];
    if (idx >= 0) {
        const float* cr = cosb + (size_t)idx * HDIM;
        const float* sr = sinb + (size_t)idx * HDIM;
        float c0 = cr[lane], c1 = cr[lane + 32];
        float s0 = sr[lane], s1 = sr[lane + 32];
        float y0 = x0 * c0 - x1 * s0;   // d<32:  x*cos - x[d+32]*sin
        float y1 = x1 * c1 + x0 * s1;   // d>=32: x*cos + x[d-32]*sin
        x0 = y0; x1 = y1;
    }
    p[lane] = x0;
    p[lane + 32] = x1;
}

// ---------------------------------------------------------------------------
// Attention. softcap bounds scores <= 50 -> fixed-shift softmax (no online max).
// Block = 128 query rows of one (b,h). K/V tiled 64 keys at a time in smem.
// ---------------------------------------------------------------------------
__global__ __launch_bounds__(128)
void attn_kernel() {
    __shared__ float Ks[64][64];
    __shared__ float Vs[64][64];

    int tid   = threadIdx.x;
    int blk   = blockIdx.x;
    int chunk = blk & 7;          // 8 chunks of 128 queries
    int bh    = blk >> 3;         // b*16 + h
    int qn    = chunk * 128 + tid;

    const float* qp = g_q + ((size_t)bh * NTOK + qn) * HDIM;
    float4 q4[16];
#pragma unroll
    for (int i = 0; i < 16; i++) q4[i] = ((const float4*)qp)[i];

    float4 a4[16];
#pragma unroll
    for (int i = 0; i < 16; i++) a4[i] = make_float4(0.f, 0.f, 0.f, 0.f);
    float l = 0.f;

    const unsigned char* mrow = g_mask + (size_t)qn * NTOK;

    for (int t0 = 0; t0 < NTOK; t0 += 64) {
        const float4* kg = (const float4*)(g_k + ((size_t)bh * NTOK + t0) * HDIM);
        const float4* vg = (const float4*)(g_v + ((size_t)bh * NTOK + t0) * HDIM);
        float4* ks4 = (float4*)Ks;
        float4* vs4 = (float4*)Vs;
#pragma unroll
        for (int i = 0; i < 8; i++) {
            ks4[tid + i * 128] = kg[tid + i * 128];
            vs4[tid + i * 128] = vg[tid + i * 128];
        }
        __syncthreads();

        for (int j = 0; j < 64; j++) {
            const float4* kr = (const float4*)Ks[j];
            float s = 0.f;
#pragma unroll
            for (int i = 0; i < 16; i++) {
                float4 kv = kr[i];
                s += q4[i].x * kv.x + q4[i].y * kv.y + q4[i].z * kv.z + q4[i].w * kv.w;
            }
            s *= 0.125f;                       // hd^-0.5
            s = 50.f * tanhf(s * 0.02f);       // soft cap
            float p = mrow[t0 + j] ? __expf(s - 50.f) : 0.f;
            l += p;
            const float4* vr = (const float4*)Vs[j];
#pragma unroll
            for (int i = 0; i < 16; i++) {
                float4 vv = vr[i];
                a4[i].x += p * vv.x; a4[i].y += p * vv.y;
                a4[i].z += p * vv.z; a4[i].w += p * vv.w;
            }
        }
        __syncthreads();
    }

    float inv = 1.f / l;
    int b = bh >> 4, h = bh & 15;
    float* op = g_o + ((size_t)(b * NTOK + qn)) * EDIM + h * HDIM;
#pragma unroll
    for (int i = 0; i < 16; i++) {
        float4 o = a4[i];
        o.x *= inv; o.y *= inv; o.z *= inv; o.w *= inv;
        ((float4*)op)[i] = o;
    }
}

// ---------------------------------------------------------------------------
extern "C" void kernel_launch(void* const* d_in, const int* in_sizes, int n_in,
                              void* d_out, int out_size) {
    const float* x    = (const float*)d_in[0];
    const float* Wq   = (const float*)d_in[1];
    const float* Wk   = (const float*)d_in[2];
    const float* Wv   = (const float*)d_in[3];
    const float* Wo   = (const float*)d_in[4];
    const float* qg   = (const float*)d_in[5];
    const float* kgm  = (const float*)d_in[6];
    const float* cosb = (const float*)d_in[7];
    const float* sinb = (const float*)d_in[8];
    const int*   ridx = (const int*)d_in[9];
    const void*  mraw = (const void*)d_in[10];
    float* out = (float*)d_out;

    mask_detect_kernel<<<1, 1024>>>((const unsigned int*)mraw);
    mask_convert_kernel<<<(NTOK * NTOK) / 256, 256>>>(mraw);

    dim3 gqkv(16, 128, 3);           // n-tiles, m-tiles, {q,k,v}
    gemm_qkv_kernel<<<gqkv, 256>>>(x, Wq, Wk, Wv);

    norm_rope_kernel<<<(2 * BHN) / 8, 256>>>(qg, kgm, cosb, sinb, ridx);

    attn_kernel<<<BATCH * NH * 8, 128>>>();

    dim3 gout(16, 128);
    gemm_out_kernel<<<gout, 256>>>(Wo, out);
}

// round 3
// speedup vs baseline: 2.7258x; 2.7258x over previous
#include <cuda_runtime.h>
#include <cuda_bf16.h>

typedef __nv_bfloat16 bf16;

#define BATCH 8
#define NTOK  1024
#define EDIM  1024
#define NH    16
#define HDIM  64
#define BH    (BATCH*NH)        // 128
#define BHN   (BH*NTOK)         // 131072
#define SSTR  40                // smem row stride in bf16 (conflict-free ldmatrix)

// ----------------------------- scratch globals ------------------------------
__device__ bf16 g_xh[8388608], g_xl[8388608];     // x split [8192][1024]
__device__ bf16 g_wh[4194304], g_wl[4194304];     // Wq,Wk,Wv,Wo split [n][k]
__device__ float g_qf[8388608], g_kf[8388608];    // q,k fp32 [B,H,N,hd]
__device__ bf16 g_qh[8388608], g_ql[8388608];     // q split (post norm+rope)
__device__ bf16 g_kh[8388608], g_kl[8388608];
__device__ bf16 g_vth[8388608], g_vtl[8388608];   // V^T split [bh][d][n]
__device__ bf16 g_eh[134217728], g_el[134217728]; // unnorm exp scores [bh][n][m]
__device__ float g_rl[131072];                    // 1/rowsum
__device__ bf16 g_oh[8388608], g_ol[8388608];     // attn out split [B*N][D]
__device__ unsigned char g_mask[NTOK*NTOK];
__device__ int g_mmode;

// ----------------------------- small helpers --------------------------------
__device__ __forceinline__ void splitf(float x, bf16& h, bf16& l) {
    h = __float2bfloat16(x);
    l = __float2bfloat16(x - __bfloat162float(h));
}

__device__ __forceinline__ void ldm4(unsigned& r0, unsigned& r1, unsigned& r2, unsigned& r3,
                                     const bf16* p) {
    unsigned a = (unsigned)__cvta_generic_to_shared(p);
    asm volatile("ldmatrix.sync.aligned.m8n8.x4.shared.b16 {%0,%1,%2,%3}, [%4];"
                 : "=r"(r0), "=r"(r1), "=r"(r2), "=r"(r3) : "r"(a));
}

__device__ __forceinline__ void mma16816(float* c, const unsigned* a, const unsigned* b) {
    asm volatile("mma.sync.aligned.m16n8k16.row.col.f32.bf16.bf16.f32 "
                 "{%0,%1,%2,%3}, {%4,%5,%6,%7}, {%8,%9}, {%0,%1,%2,%3};"
                 : "+f"(c[0]), "+f"(c[1]), "+f"(c[2]), "+f"(c[3])
                 : "r"(a[0]), "r"(a[1]), "r"(a[2]), "r"(a[3]), "r"(b[0]), "r"(b[1]));
}

__device__ __forceinline__ void cpasync16(const void* g, bf16* s) {
    unsigned sa = (unsigned)__cvta_generic_to_shared(s);
    asm volatile("cp.async.cg.shared.global [%0], [%1], 16;" :: "r"(sa), "l"(g) : "memory");
}

// ----------------------------------------------------------------------------
// bf16 split GEMM mainloop: C += Ah*Bh + Ah*Bl + Al*Bh  (NT GEMM, B is [n][k])
// BM=128, BN in {128,64}. 256 threads = 8 warps (4 along M x 2 along N).
// K chunk 32, cp.async double buffered.
// ----------------------------------------------------------------------------
template<int BN>
__device__ __forceinline__ void gemm_main3(
    const bf16* __restrict__ Ah, const bf16* __restrict__ Al, int lda,
    const bf16* __restrict__ Bh, const bf16* __restrict__ Bl, int ldb,
    int K, float (&acc)[2][BN/16][4])
{
    constexpr int NT  = BN / 16;      // n8 tiles per warp
    constexpr int ASZ = 128 * SSTR;
    constexpr int BSZ = BN * SSTR;
    constexpr int STG = 2 * ASZ + 2 * BSZ;
    extern __shared__ __align__(16) char smem_raw[];
    bf16* sm = (bf16*)smem_raw;

    int tid = threadIdx.x, l = tid & 31, wid = tid >> 5;
    int wm = (wid & 3) * 32, wn = (wid >> 2) * (BN / 2);

    auto load_stage = [&](int st, int k0) {
        bf16* sAh = sm + st * STG;
        bf16* sAl = sAh + ASZ;
        bf16* sBh = sAl + ASZ;
        bf16* sBl = sBh + BSZ;
        for (int c = tid; c < 512; c += 256) {
            int r = c >> 2, co = (c & 3) * 8;
            size_t go = (size_t)r * lda + k0 + co;
            cpasync16(Ah + go, sAh + r * SSTR + co);
            cpasync16(Al + go, sAl + r * SSTR + co);
        }
        for (int c = tid; c < BN * 4; c += 256) {
            int r = c >> 2, co = (c & 3) * 8;
            size_t go = (size_t)r * ldb + k0 + co;
            cpasync16(Bh + go, sBh + r * SSTR + co);
            cpasync16(Bl + go, sBl + r * SSTR + co);
        }
        asm volatile("cp.async.commit_group;" ::: "memory");
    };

    int nk = K >> 5;
    load_stage(0, 0);
    for (int t = 0; t < nk; t++) {
        if (t + 1 < nk) {
            load_stage((t + 1) & 1, (t + 1) * 32);
            asm volatile("cp.async.wait_group 1;" ::: "memory");
        } else {
            asm volatile("cp.async.wait_group 0;" ::: "memory");
        }
        __syncthreads();
        const bf16* sAh = sm + (t & 1) * STG;
        const bf16* sAl = sAh + ASZ;
        const bf16* sBh = sAl + ASZ;
        const bf16* sBl = sBh + BSZ;
        int an = l & 15, ak = (l >> 4) * 8;
        int bn = ((l >> 4) & 1) * 8 + (l & 7), bk = ((l >> 3) & 1) * 8;
#pragma unroll
        for (int kk = 0; kk < 32; kk += 16) {
            unsigned fAh[2][4], fAl[2][4], fBh[NT][2], fBl[NT][2];
#pragma unroll
            for (int i = 0; i < 2; i++) {
                const bf16* pa = sAh + (wm + i * 16 + an) * SSTR + kk + ak;
                ldm4(fAh[i][0], fAh[i][1], fAh[i][2], fAh[i][3], pa);
                const bf16* pl = sAl + (wm + i * 16 + an) * SSTR + kk + ak;
                ldm4(fAl[i][0], fAl[i][1], fAl[i][2], fAl[i][3], pl);
            }
#pragma unroll
            for (int jj = 0; jj < NT / 2; jj++) {
                const bf16* pb = sBh + (wn + jj * 16 + bn) * SSTR + kk + bk;
                ldm4(fBh[2*jj][0], fBh[2*jj][1], fBh[2*jj+1][0], fBh[2*jj+1][1], pb);
                const bf16* pb2 = sBl + (wn + jj * 16 + bn) * SSTR + kk + bk;
                ldm4(fBl[2*jj][0], fBl[2*jj][1], fBl[2*jj+1][0], fBl[2*jj+1][1], pb2);
            }
#pragma unroll
            for (int i = 0; i < 2; i++)
#pragma unroll
                for (int j = 0; j < NT; j++) {
                    mma16816(acc[i][j], fAh[i], fBh[j]);
                    mma16816(acc[i][j], fAh[i], fBl[j]);
                    mma16816(acc[i][j], fAl[i], fBh[j]);
                }
        }
        __syncthreads();
    }
}

// ----------------------------- conversions ----------------------------------
__global__ __launch_bounds__(256) void k_split_x(const float* __restrict__ src) {
    size_t i = ((size_t)blockIdx.x * 256 + threadIdx.x) * 4;
    float4 v = *(const float4*)(src + i);
    __nv_bfloat162 h01, h23, l01, l23;
    splitf(v.x, h01.x, l01.x); splitf(v.y, h01.y, l01.y);
    splitf(v.z, h23.x, l23.x); splitf(v.w, h23.y, l23.y);
    *(__nv_bfloat162*)(g_xh + i)     = h01; *(__nv_bfloat162*)(g_xh + i + 2) = h23;
    *(__nv_bfloat162*)(g_xl + i)     = l01; *(__nv_bfloat162*)(g_xl + i + 2) = l23;
}

__global__ __launch_bounds__(256) void k_split_w(const float* __restrict__ src, int which) {
    size_t base = (size_t)which * 1048576;
    size_t i = ((size_t)blockIdx.x * 256 + threadIdx.x) * 4;
    float4 v = *(const float4*)(src + i);
    __nv_bfloat162 h01, h23, l01, l23;
    splitf(v.x, h01.x, l01.x); splitf(v.y, h01.y, l01.y);
    splitf(v.z, h23.x, l23.x); splitf(v.w, h23.y, l23.y);
    *(__nv_bfloat162*)(g_wh + base + i)     = h01; *(__nv_bfloat162*)(g_wh + base + i + 2) = h23;
    *(__nv_bfloat162*)(g_wl + base + i)     = l01; *(__nv_bfloat162*)(g_wl + base + i + 2) = l23;
}

// ----------------------------- mask handling --------------------------------
__global__ __launch_bounds__(1024) void mask_detect_kernel(const unsigned int* __restrict__ m) {
    __shared__ int s_int, s_flt;
    if (threadIdx.x == 0) { s_int = 1; s_flt = 1; }
    __syncthreads();
    int bad_int = 0, bad_flt = 0;
    for (int i = threadIdx.x; i < 262144; i += 1024) {
        unsigned int w = m[i];
        if (w > 1u) bad_int = 1;
        if (w != 0u && w != 0x3F800000u) bad_flt = 1;
    }
    if (bad_int) atomicAnd(&s_int, 0);
    if (bad_flt) atomicAnd(&s_flt, 0);
    __syncthreads();
    if (threadIdx.x == 0) g_mmode = s_int ? 1 : (s_flt ? 2 : 0);
}

__global__ __launch_bounds__(256) void mask_convert_kernel(const void* __restrict__ mraw) {
    int mode = g_mmode;
    int i = blockIdx.x * 256 + threadIdx.x;
    unsigned char v;
    if (mode == 1)      v = (unsigned char)(((const int*)mraw)[i] != 0);
    else if (mode == 2) v = (unsigned char)(((const float*)mraw)[i] != 0.f);
    else                v = (unsigned char)(((const unsigned char*)mraw)[i] != 0);
    g_mask[i] = v;
}

// ----------------------------- QKV projection -------------------------------
__global__ __launch_bounds__(256) void k_gemm_qkv() {
    int z = blockIdx.z;
    int m0 = blockIdx.y * 128, n0 = blockIdx.x * 128;
    float acc[2][8][4];
#pragma unroll
    for (int i = 0; i < 2; i++)
#pragma unroll
        for (int j = 0; j < 8; j++)
#pragma unroll
            for (int q = 0; q < 4; q++) acc[i][j][q] = 0.f;

    gemm_main3<128>(g_xh + (size_t)m0 * 1024, g_xl + (size_t)m0 * 1024, 1024,
                    g_wh + (size_t)z * 1048576 + (size_t)n0 * 1024,
                    g_wl + (size_t)z * 1048576 + (size_t)n0 * 1024, 1024,
                    1024, acc);

    int l = threadIdx.x & 31, wid = threadIdx.x >> 5;
    int wm = (wid & 3) * 32, wn = (wid >> 2) * 64;
#pragma unroll
    for (int i = 0; i < 2; i++)
#pragma unroll
        for (int j = 0; j < 8; j++) {
            int r = m0 + wm + i * 16 + (l >> 2);
            int c = n0 + wn + j * 8 + (l & 3) * 2;
            if (z < 2) {
                float* dst = z ? g_kf : g_qf;
#pragma unroll
                for (int h2 = 0; h2 < 2; h2++) {
                    int rr = r + h2 * 8;
                    int b = rr >> 10, nn = rr & 1023;
                    int hh = c >> 6, d = c & 63;
                    size_t o = (((size_t)(b * NH + hh) * NTOK) + nn) * HDIM + d;
                    dst[o]     = acc[i][j][h2 * 2 + 0];
                    dst[o + 1] = acc[i][j][h2 * 2 + 1];
                }
            } else {
#pragma unroll
                for (int h2 = 0; h2 < 2; h2++)
#pragma unroll
                    for (int q = 0; q < 2; q++) {
                        int rr = r + h2 * 8, cc = c + q;
                        int b = rr >> 10, nn = rr & 1023;
                        int hh = cc >> 6, d = cc & 63;
                        size_t o = (((size_t)(b * NH + hh) * HDIM) + d) * NTOK + nn;
                        splitf(acc[i][j][h2 * 2 + q], g_vth[o], g_vtl[o]);
                    }
            }
        }
}

// ----------------------------- QKNorm + RoPE --------------------------------
__global__ __launch_bounds__(256)
void norm_rope_kernel(const float* __restrict__ qg, const float* __restrict__ kgamma,
                      const float* __restrict__ cosb, const float* __restrict__ sinb,
                      const int* __restrict__ ridx) {
    int warp = (blockIdx.x * blockDim.x + threadIdx.x) >> 5;
    int lane = threadIdx.x & 31;
    int which = (warp >= BHN) ? 1 : 0;
    int r = warp - which * BHN;
    int n = r & (NTOK - 1);

    const float* p = (which ? g_kf : g_qf) + (size_t)r * HDIM;
    const float* gamma = which ? kgamma : qg;

    float x0 = p[lane];
    float x1 = p[lane + 32];
    float ss = x0 * x0 + x1 * x1;
#pragma unroll
    for (int o = 16; o; o >>= 1) ss += __shfl_xor_sync(0xffffffffu, ss, o);
    float rms = rsqrtf(ss * (1.0f / 64.0f) + 1e-6f);
    x0 *= rms * gamma[lane];
    x1 *= rms * gamma[lane + 32];

    int idx = ridx[n];
    if (idx >= 0) {
        const float* cr = cosb + (size_t)idx * HDIM;
        const float* sr = sinb + (size_t)idx * HDIM;
        float c0 = cr[lane], c1 = cr[lane + 32];
        float s0 = sr[lane], s1 = sr[lane + 32];
        float y0 = x0 * c0 - x1 * s0;
        float y1 = x1 * c1 + x0 * s1;
        x0 = y0; x1 = y1;
    }
    bf16 *h0, *l0;
    if (which) { h0 = g_kh; l0 = g_kl; } else { h0 = g_qh; l0 = g_ql; }
    size_t o = (size_t)r * HDIM;
    splitf(x0, h0[o + lane],      l0[o + lane]);
    splitf(x1, h0[o + lane + 32], l0[o + lane + 32]);
}

// ----------------------------- score GEMM + softcap + exp -------------------
__global__ __launch_bounds__(256) void k_score() {
    int z = blockIdx.z;              // bh
    int m0 = blockIdx.y * 128, n0 = blockIdx.x * 128;
    size_t base = (size_t)z * (NTOK * HDIM);
    float acc[2][8][4];
#pragma unroll
    for (int i = 0; i < 2; i++)
#pragma unroll
        for (int j = 0; j < 8; j++)
#pragma unroll
            for (int q = 0; q < 4; q++) acc[i][j][q] = 0.f;

    gemm_main3<128>(g_qh + base + (size_t)m0 * 64, g_ql + base + (size_t)m0 * 64, 64,
                    g_kh + base + (size_t)n0 * 64, g_kl + base + (size_t)n0 * 64, 64,
                    64, acc);

    int l = threadIdx.x & 31, wid = threadIdx.x >> 5;
    int wm = (wid & 3) * 32, wn = (wid >> 2) * 64;
#pragma unroll
    for (int i = 0; i < 2; i++)
#pragma unroll
        for (int j = 0; j < 8; j++) {
            int r = m0 + wm + i * 16 + (l >> 2);
            int c = n0 + wn + j * 8 + (l & 3) * 2;
#pragma unroll
            for (int h2 = 0; h2 < 2; h2++) {
                int rr = r + h2 * 8;
                __nv_bfloat162 eh2, el2;
#pragma unroll
                for (int q = 0; q < 2; q++) {
                    int cc = c + q;
                    float s = acc[i][j][h2 * 2 + q] * 0.125f;       // hd^-0.5
                    float t = __expf(s * (2.0f / 50.0f));
                    float th = 1.0f - __fdividef(2.0f, t + 1.0f);  // tanh(s/50)
                    float capped = 50.0f * th;
                    float pv = g_mask[(size_t)rr * NTOK + cc] ? __expf(capped - 50.0f) : 0.0f;
                    bf16 hh, ll; splitf(pv, hh, ll);
                    if (q == 0) { eh2.x = hh; el2.x = ll; } else { eh2.y = hh; el2.y = ll; }
                }
                size_t o = ((size_t)z * NTOK + rr) * NTOK + c;
                *(__nv_bfloat162*)(g_eh + o) = eh2;
                *(__nv_bfloat162*)(g_el + o) = el2;
            }
        }
}

// ----------------------------- row sums -------------------------------------
__global__ __launch_bounds__(256) void k_rowsum() {
    int row = blockIdx.x * 8 + (threadIdx.x >> 5);
    int l = threadIdx.x & 31;
    const uint4* ph = (const uint4*)(g_eh + (size_t)row * NTOK);
    const uint4* pl = (const uint4*)(g_el + (size_t)row * NTOK);
    float s = 0.f;
    for (int i = l; i < 128; i += 32) {
        uint4 a = ph[i], b = pl[i];
        const __nv_bfloat162* pa = (const __nv_bfloat162*)&a;
        const __nv_bfloat162* pb = (const __nv_bfloat162*)&b;
#pragma unroll
        for (int q = 0; q < 4; q++) {
            float2 fa = __bfloat1622float2(pa[q]);
            float2 fb = __bfloat1622float2(pb[q]);
            s += fa.x + fa.y + fb.x + fb.y;
        }
    }
#pragma unroll
    for (int o = 16; o; o >>= 1) s += __shfl_xor_sync(0xffffffffu, s, o);
    if (l == 0) g_rl[row] = 1.0f / s;
}

// ----------------------------- PV GEMM --------------------------------------
__global__ __launch_bounds__(256) void k_pv() {
    int z = blockIdx.z;
    int m0 = blockIdx.y * 128;
    float acc[2][4][4];
#pragma unroll
    for (int i = 0; i < 2; i++)
#pragma unroll
        for (int j = 0; j < 4; j++)
#pragma unroll
            for (int q = 0; q < 4; q++) acc[i][j][q] = 0.f;

    gemm_main3<64>(g_eh + (size_t)z * (NTOK * NTOK) + (size_t)m0 * NTOK,
                   g_el + (size_t)z * (NTOK * NTOK) + (size_t)m0 * NTOK, NTOK,
                   g_vth + (size_t)z * (HDIM * NTOK),
                   g_vtl + (size_t)z * (HDIM * NTOK), NTOK,
                   NTOK, acc);

    int l = threadIdx.x & 31, wid = threadIdx.x >> 5;
    int wm = (wid & 3) * 32, wn = (wid >> 2) * 32;
    int b = z >> 4, h = z & 15;
#pragma unroll
    for (int i = 0; i < 2; i++)
#pragma unroll
        for (int j = 0; j < 4; j++) {
            int r = m0 + wm + i * 16 + (l >> 2);
            int c = wn + j * 8 + (l & 3) * 2;          // d in [0,64)
#pragma unroll
            for (int h2 = 0; h2 < 2; h2++) {
                int rr = r + h2 * 8;
                float rv = g_rl[z * NTOK + rr];
                __nv_bfloat162 oh2, ol2;
#pragma unroll
                for (int q = 0; q < 2; q++) {
                    float v = acc[i][j][h2 * 2 + q] * rv;
                    bf16 hh, ll; splitf(v, hh, ll);
                    if (q == 0) { oh2.x = hh; ol2.x = ll; } else { oh2.y = hh; ol2.y = ll; }
                }
                size_t o = ((size_t)b * NTOK + rr) * EDIM + h * HDIM + c;
                *(__nv_bfloat162*)(g_oh + o) = oh2;
                *(__nv_bfloat162*)(g_ol + o) = ol2;
            }
        }
}

// ----------------------------- output projection ----------------------------
__global__ __launch_bounds__(256) void k_out(float* __restrict__ out) {
    int m0 = blockIdx.y * 128, n0 = blockIdx.x * 128;
    float acc[2][8][4];
#pragma unroll
    for (int i = 0; i < 2; i++)
#pragma unroll
        for (int j = 0; j < 8; j++)
#pragma unroll
            for (int q = 0; q < 4; q++) acc[i][j][q] = 0.f;

    gemm_main3<128>(g_oh + (size_t)m0 * 1024, g_ol + (size_t)m0 * 1024, 1024,
                    g_wh + (size_t)3 * 1048576 + (size_t)n0 * 1024,
                    g_wl + (size_t)3 * 1048576 + (size_t)n0 * 1024, 1024,
                    1024, acc);

    int l = threadIdx.x & 31, wid = threadIdx.x >> 5;
    int wm = (wid & 3) * 32, wn = (wid >> 2) * 64;
#pragma unroll
    for (int i = 0; i < 2; i++)
#pragma unroll
        for (int j = 0; j < 8; j++) {
            int r = m0 + wm + i * 16 + (l >> 2);
            int c = n0 + wn + j * 8 + (l & 3) * 2;
#pragma unroll
            for (int h2 = 0; h2 < 2; h2++) {
                int rr = r + h2 * 8;
                out[(size_t)rr * EDIM + c]     = acc[i][j][h2 * 2 + 0];
                out[(size_t)rr * EDIM + c + 1] = acc[i][j][h2 * 2 + 1];
            }
        }
}

// ----------------------------------------------------------------------------
extern "C" void kernel_launch(void* const* d_in, const int* in_sizes, int n_in,
                              void* d_out, int out_size) {
    const float* x    = (const float*)d_in[0];
    const float* Wq   = (const float*)d_in[1];
    const float* Wk   = (const float*)d_in[2];
    const float* Wv   = (const float*)d_in[3];
    const float* Wo   = (const float*)d_in[4];
    const float* qg   = (const float*)d_in[5];
    const float* kgm  = (const float*)d_in[6];
    const float* cosb = (const float*)d_in[7];
    const float* sinb = (const float*)d_in[8];
    const int*   ridx = (const int*)d_in[9];
    const void*  mraw = (const void*)d_in[10];
    float* out = (float*)d_out;

    cudaFuncSetAttribute(k_gemm_qkv, cudaFuncAttributeMaxDynamicSharedMemorySize, 81920);
    cudaFuncSetAttribute(k_score,    cudaFuncAttributeMaxDynamicSharedMemorySize, 81920);
    cudaFuncSetAttribute(k_pv,       cudaFuncAttributeMaxDynamicSharedMemorySize, 61440);
    cudaFuncSetAttribute(k_out,      cudaFuncAttributeMaxDynamicSharedMemorySize, 81920);

    mask_detect_kernel<<<1, 1024>>>((const unsigned int*)mraw);
    mask_convert_kernel<<<4096, 256>>>(mraw);

    k_split_x<<<8192, 256>>>(x);
    k_split_w<<<1024, 256>>>(Wq, 0);
    k_split_w<<<1024, 256>>>(Wk, 1);
    k_split_w<<<1024, 256>>>(Wv, 2);
    k_split_w<<<1024, 256>>>(Wo, 3);

    k_gemm_qkv<<<dim3(8, 64, 3), 256, 81920>>>();

    norm_rope_kernel<<<(2 * BHN) / 8, 256>>>(qg, kgm, cosb, sinb, ridx);

    k_score<<<dim3(8, 8, BH), 256, 81920>>>();
    k_rowsum<<<BHN / 8, 256>>>();
    k_pv<<<dim3(1, 8, BH), 256, 61440>>>();

    k_out<<<dim3(8, 64), 256, 81920>>>(out);
}

// round 4
// speedup vs baseline: 3.0645x; 1.1243x over previous
#include <cuda_runtime.h>
#include <cuda_bf16.h>

typedef __nv_bfloat16 bf16;

#define BATCH 8
#define NTOK  1024
#define EDIM  1024
#define NH    16
#define HDIM  64
#define BH    (BATCH*NH)        // 128
#define BHN   (BH*NTOK)         // 131072
#define SSTR  40                // gemm smem row stride (bf16)
#define ASTR  72                // attn smem row stride (bf16), conflict-free
#define STG_T (4*64*ASTR)       // bf16 per attn stage (Kh,Kl,Vh,Vl)

// ----------------------------- scratch globals ------------------------------
__device__ bf16 g_xh[8388608], g_xl[8388608];     // x split [8192][1024]
__device__ bf16 g_wh[4194304], g_wl[4194304];     // Wq,Wk,Wv,Wo split [n][k]
__device__ float g_qf[8388608], g_kf[8388608];    // q,k fp32 [B,H,N,hd]
__device__ bf16 g_qh[8388608], g_ql[8388608];     // q split (prescaled by 0.125)
__device__ bf16 g_kh[8388608], g_kl[8388608];
__device__ bf16 g_vth[8388608], g_vtl[8388608];   // V^T split [bh][d][n]
__device__ bf16 g_oh[8388608], g_ol[8388608];     // attn out split [B*N][D]
__device__ unsigned char g_mask[NTOK*NTOK];
__device__ int g_mmode;

// ----------------------------- small helpers --------------------------------
__device__ __forceinline__ void splitf(float x, bf16& h, bf16& l) {
    h = __float2bfloat16(x);
    l = __float2bfloat16(x - __bfloat162float(h));
}

__device__ __forceinline__ void ldm4(unsigned& r0, unsigned& r1, unsigned& r2, unsigned& r3,
                                     const bf16* p) {
    unsigned a = (unsigned)__cvta_generic_to_shared(p);
    asm volatile("ldmatrix.sync.aligned.m8n8.x4.shared.b16 {%0,%1,%2,%3}, [%4];"
                 : "=r"(r0), "=r"(r1), "=r"(r2), "=r"(r3) : "r"(a));
}

__device__ __forceinline__ void mma16816(float* c, const unsigned* a, const unsigned* b) {
    asm volatile("mma.sync.aligned.m16n8k16.row.col.f32.bf16.bf16.f32 "
                 "{%0,%1,%2,%3}, {%4,%5,%6,%7}, {%8,%9}, {%0,%1,%2,%3};"
                 : "+f"(c[0]), "+f"(c[1]), "+f"(c[2]), "+f"(c[3])
                 : "r"(a[0]), "r"(a[1]), "r"(a[2]), "r"(a[3]), "r"(b[0]), "r"(b[1]));
}

__device__ __forceinline__ void cpasync16(const void* g, void* s) {
    unsigned sa = (unsigned)__cvta_generic_to_shared(s);
    asm volatile("cp.async.cg.shared.global [%0], [%1], 16;" :: "r"(sa), "l"(g) : "memory");
}

__device__ __forceinline__ float ex2a(float x) {
    float r; asm("ex2.approx.ftz.f32 %0, %1;" : "=f"(r) : "f"(x)); return r;
}

__device__ __forceinline__ unsigned pack2(bf16 a, bf16 b) {
    __nv_bfloat162 t; t.x = a; t.y = b;
    return *(unsigned*)&t;
}

// ----------------------------------------------------------------------------
// bf16 split GEMM mainloop: C += Ah*Bh + Ah*Bl + Al*Bh  (NT GEMM, B is [n][k])
// ----------------------------------------------------------------------------
template<int BN>
__device__ __forceinline__ void gemm_main3(
    const bf16* __restrict__ Ah, const bf16* __restrict__ Al, int lda,
    const bf16* __restrict__ Bh, const bf16* __restrict__ Bl, int ldb,
    int K, float (&acc)[2][BN/16][4])
{
    constexpr int NT  = BN / 16;
    constexpr int ASZ = 128 * SSTR;
    constexpr int BSZ = BN * SSTR;
    constexpr int STG = 2 * ASZ + 2 * BSZ;
    extern __shared__ __align__(16) char smem_raw[];
    bf16* sm = (bf16*)smem_raw;

    int tid = threadIdx.x, l = tid & 31, wid = tid >> 5;
    int wm = (wid & 3) * 32, wn = (wid >> 2) * (BN / 2);

    auto load_stage = [&](int st, int k0) {
        bf16* sAh = sm + st * STG;
        bf16* sAl = sAh + ASZ;
        bf16* sBh = sAl + ASZ;
        bf16* sBl = sBh + BSZ;
        for (int c = tid; c < 512; c += 256) {
            int r = c >> 2, co = (c & 3) * 8;
            size_t go = (size_t)r * lda + k0 + co;
            cpasync16(Ah + go, sAh + r * SSTR + co);
            cpasync16(Al + go, sAl + r * SSTR + co);
        }
        for (int c = tid; c < BN * 4; c += 256) {
            int r = c >> 2, co = (c & 3) * 8;
            size_t go = (size_t)r * ldb + k0 + co;
            cpasync16(Bh + go, sBh + r * SSTR + co);
            cpasync16(Bl + go, sBl + r * SSTR + co);
        }
        asm volatile("cp.async.commit_group;" ::: "memory");
    };

    int nk = K >> 5;
    load_stage(0, 0);
    for (int t = 0; t < nk; t++) {
        if (t + 1 < nk) {
            load_stage((t + 1) & 1, (t + 1) * 32);
            asm volatile("cp.async.wait_group 1;" ::: "memory");
        } else {
            asm volatile("cp.async.wait_group 0;" ::: "memory");
        }
        __syncthreads();
        const bf16* sAh = sm + (t & 1) * STG;
        const bf16* sAl = sAh + ASZ;
        const bf16* sBh = sAl + ASZ;
        const bf16* sBl = sBh + BSZ;
        int an = l & 15, ak = (l >> 4) * 8;
        int bn = ((l >> 4) & 1) * 8 + (l & 7), bk = ((l >> 3) & 1) * 8;
#pragma unroll
        for (int kk = 0; kk < 32; kk += 16) {
            unsigned fAh[2][4], fAl[2][4], fBh[NT][2], fBl[NT][2];
#pragma unroll
            for (int i = 0; i < 2; i++) {
                const bf16* pa = sAh + (wm + i * 16 + an) * SSTR + kk + ak;
                ldm4(fAh[i][0], fAh[i][1], fAh[i][2], fAh[i][3], pa);
                const bf16* pl = sAl + (wm + i * 16 + an) * SSTR + kk + ak;
                ldm4(fAl[i][0], fAl[i][1], fAl[i][2], fAl[i][3], pl);
            }
#pragma unroll
            for (int jj = 0; jj < NT / 2; jj++) {
                const bf16* pb = sBh + (wn + jj * 16 + bn) * SSTR + kk + bk;
                ldm4(fBh[2*jj][0], fBh[2*jj][1], fBh[2*jj+1][0], fBh[2*jj+1][1], pb);
                const bf16* pb2 = sBl + (wn + jj * 16 + bn) * SSTR + kk + bk;
                ldm4(fBl[2*jj][0], fBl[2*jj][1], fBl[2*jj+1][0], fBl[2*jj+1][1], pb2);
            }
#pragma unroll
            for (int i = 0; i < 2; i++)
#pragma unroll
                for (int j = 0; j < NT; j++) {
                    mma16816(acc[i][j], fAh[i], fBh[j]);
                    mma16816(acc[i][j], fAh[i], fBl[j]);
                    mma16816(acc[i][j], fAl[i], fBh[j]);
                }
        }
        __syncthreads();
    }
}

// ----------------------------- conversions ----------------------------------
__global__ __launch_bounds__(256) void k_split_x(const float* __restrict__ src) {
    size_t i = ((size_t)blockIdx.x * 256 + threadIdx.x) * 4;
    float4 v = *(const float4*)(src + i);
    __nv_bfloat162 h01, h23, l01, l23;
    splitf(v.x, h01.x, l01.x); splitf(v.y, h01.y, l01.y);
    splitf(v.z, h23.x, l23.x); splitf(v.w, h23.y, l23.y);
    *(__nv_bfloat162*)(g_xh + i)     = h01; *(__nv_bfloat162*)(g_xh + i + 2) = h23;
    *(__nv_bfloat162*)(g_xl + i)     = l01; *(__nv_bfloat162*)(g_xl + i + 2) = l23;
}

__global__ __launch_bounds__(256) void k_split_w(const float* __restrict__ src, int which) {
    size_t base = (size_t)which * 1048576;
    size_t i = ((size_t)blockIdx.x * 256 + threadIdx.x) * 4;
    float4 v = *(const float4*)(src + i);
    __nv_bfloat162 h01, h23, l01, l23;
    splitf(v.x, h01.x, l01.x); splitf(v.y, h01.y, l01.y);
    splitf(v.z, h23.x, l23.x); splitf(v.w, h23.y, l23.y);
    *(__nv_bfloat162*)(g_wh + base + i)     = h01; *(__nv_bfloat162*)(g_wh + base + i + 2) = h23;
    *(__nv_bfloat162*)(g_wl + base + i)     = l01; *(__nv_bfloat162*)(g_wl + base + i + 2) = l23;
}

// ----------------------------- mask handling --------------------------------
__global__ __launch_bounds__(1024) void mask_detect_kernel(const unsigned int* __restrict__ m) {
    __shared__ int s_int, s_flt;
    if (threadIdx.x == 0) { s_int = 1; s_flt = 1; }
    __syncthreads();
    int bad_int = 0, bad_flt = 0;
    for (int i = threadIdx.x; i < 262144; i += 1024) {
        unsigned int w = m[i];
        if (w > 1u) bad_int = 1;
        if (w != 0u && w != 0x3F800000u) bad_flt = 1;
    }
    if (bad_int) atomicAnd(&s_int, 0);
    if (bad_flt) atomicAnd(&s_flt, 0);
    __syncthreads();
    if (threadIdx.x == 0) g_mmode = s_int ? 1 : (s_flt ? 2 : 0);
}

__global__ __launch_bounds__(256) void mask_convert_kernel(const void* __restrict__ mraw) {
    int mode = g_mmode;
    int i = blockIdx.x * 256 + threadIdx.x;
    unsigned char v;
    if (mode == 1)      v = (unsigned char)(((const int*)mraw)[i] != 0);
    else if (mode == 2) v = (unsigned char)(((const float*)mraw)[i] != 0.f);
    else                v = (unsigned char)(((const unsigned char*)mraw)[i] != 0);
    g_mask[i] = v;
}

// ----------------------------- QKV projection -------------------------------
__global__ __launch_bounds__(256) void k_gemm_qkv() {
    int z = blockIdx.z;
    int m0 = blockIdx.y * 128, n0 = blockIdx.x * 128;
    float acc[2][8][4];
#pragma unroll
    for (int i = 0; i < 2; i++)
#pragma unroll
        for (int j = 0; j < 8; j++)
#pragma unroll
            for (int q = 0; q < 4; q++) acc[i][j][q] = 0.f;

    gemm_main3<128>(g_xh + (size_t)m0 * 1024, g_xl + (size_t)m0 * 1024, 1024,
                    g_wh + (size_t)z * 1048576 + (size_t)n0 * 1024,
                    g_wl + (size_t)z * 1048576 + (size_t)n0 * 1024, 1024,
                    1024, acc);

    int l = threadIdx.x & 31, wid = threadIdx.x >> 5;
    int wm = (wid & 3) * 32, wn = (wid >> 2) * 64;
#pragma unroll
    for (int i = 0; i < 2; i++)
#pragma unroll
        for (int j = 0; j < 8; j++) {
            int r = m0 + wm + i * 16 + (l >> 2);
            int c = n0 + wn + j * 8 + (l & 3) * 2;
            if (z < 2) {
                float* dst = z ? g_kf : g_qf;
#pragma unroll
                for (int h2 = 0; h2 < 2; h2++) {
                    int rr = r + h2 * 8;
                    int b = rr >> 10, nn = rr & 1023;
                    int hh = c >> 6, d = c & 63;
                    size_t o = (((size_t)(b * NH + hh) * NTOK) + nn) * HDIM + d;
                    dst[o]     = acc[i][j][h2 * 2 + 0];
                    dst[o + 1] = acc[i][j][h2 * 2 + 1];
                }
            } else {
#pragma unroll
                for (int h2 = 0; h2 < 2; h2++)
#pragma unroll
                    for (int q = 0; q < 2; q++) {
                        int rr = r + h2 * 8, cc = c + q;
                        int b = rr >> 10, nn = rr & 1023;
                        int hh = cc >> 6, d = cc & 63;
                        size_t o = (((size_t)(b * NH + hh) * HDIM) + d) * NTOK + nn;
                        splitf(acc[i][j][h2 * 2 + q], g_vth[o], g_vtl[o]);
                    }
            }
        }
}

// ----------------------------- QKNorm + RoPE --------------------------------
__global__ __launch_bounds__(256)
void norm_rope_kernel(const float* __restrict__ qg, const float* __restrict__ kgamma,
                      const float* __restrict__ cosb, const float* __restrict__ sinb,
                      const int* __restrict__ ridx) {
    int warp = (blockIdx.x * blockDim.x + threadIdx.x) >> 5;
    int lane = threadIdx.x & 31;
    int which = (warp >= BHN) ? 1 : 0;
    int r = warp - which * BHN;
    int n = r & (NTOK - 1);

    const float* p = (which ? g_kf : g_qf) + (size_t)r * HDIM;
    const float* gamma = which ? kgamma : qg;

    float x0 = p[lane];
    float x1 = p[lane + 32];
    float ss = x0 * x0 + x1 * x1;
#pragma unroll
    for (int o = 16; o; o >>= 1) ss += __shfl_xor_sync(0xffffffffu, ss, o);
    float rms = rsqrtf(ss * (1.0f / 64.0f) + 1e-6f);
    x0 *= rms * gamma[lane];
    x1 *= rms * gamma[lane + 32];

    int idx = ridx[n];
    if (idx >= 0) {
        const float* cr = cosb + (size_t)idx * HDIM;
        const float* sr = sinb + (size_t)idx * HDIM;
        float c0 = cr[lane], c1 = cr[lane + 32];
        float s0 = sr[lane], s1 = sr[lane + 32];
        float y0 = x0 * c0 - x1 * s0;
        float y1 = x1 * c1 + x0 * s1;
        x0 = y0; x1 = y1;
    }
    // fold softmax scale hd^-0.5 = 0.125 into q
    float sc = which ? 1.0f : 0.125f;
    x0 *= sc; x1 *= sc;
    bf16 *h0, *l0;
    if (which) { h0 = g_kh; l0 = g_kl; } else { h0 = g_qh; l0 = g_ql; }
    size_t o = (size_t)r * HDIM;
    splitf(x0, h0[o + lane],      l0[o + lane]);
    splitf(x1, h0[o + lane + 32], l0[o + lane + 32]);
}

// ----------------------------------------------------------------------------
// Fused flash attention: S = QK^T (split mma) -> softcap -> exp(s-50) -> P.V^T
// Block: 128 queries of one (b,h). 8 warps x 16 q rows. 64-key tiles, double
// buffered. P stays in registers (C-frag == A-frag identity).
// ----------------------------------------------------------------------------
__global__ __launch_bounds__(256, 1) void k_attn() {
    extern __shared__ __align__(16) char smem_raw[];
    bf16* sm = (bf16*)smem_raw;
    unsigned char* smaskb = (unsigned char*)(sm + 2 * STG_T);

    int tid = threadIdx.x, l = tid & 31, wid = tid >> 5;
    int wm = wid * 16;
    int q0 = blockIdx.x * 128;
    int bh = blockIdx.y;
    int b = bh >> 4, h = bh & 15;
    size_t kvbase = (size_t)bh * (NTOK * HDIM);

    // ---- stage Q into smem (reusing stage-0 buffer), load fragments ----
    {
        const bf16* gQh = g_qh + kvbase + (size_t)q0 * HDIM;
        const bf16* gQl = g_ql + kvbase + (size_t)q0 * HDIM;
        bf16* sQh = sm;
        bf16* sQl = sm + 128 * ASTR;
        for (int c = tid; c < 1024; c += 256) {
            int r = c >> 3, co = (c & 7) * 8;
            cpasync16(gQh + r * 64 + co, sQh + r * ASTR + co);
            cpasync16(gQl + r * 64 + co, sQl + r * ASTR + co);
        }
        asm volatile("cp.async.commit_group;" ::: "memory");
        asm volatile("cp.async.wait_group 0;" ::: "memory");
        __syncthreads();
    }
    unsigned qh[4][4], ql[4][4];
    {
        int an = l & 15, ak = (l >> 4) * 8;
#pragma unroll
        for (int kt = 0; kt < 4; kt++) {
            ldm4(qh[kt][0], qh[kt][1], qh[kt][2], qh[kt][3],
                 sm + (wm + an) * ASTR + kt * 16 + ak);
            ldm4(ql[kt][0], ql[kt][1], ql[kt][2], ql[kt][3],
                 sm + 128 * ASTR + (wm + an) * ASTR + kt * 16 + ak);
        }
    }
    __syncthreads();   // Q regs read; buffers may be reused

    float o_acc[8][4];
#pragma unroll
    for (int j = 0; j < 8; j++)
#pragma unroll
        for (int v = 0; v < 4; v++) o_acc[j][v] = 0.f;
    float ls0 = 0.f, ls1 = 0.f;

    auto load_tile = [&](int s, int t0) {
        bf16* sKh = sm + s * STG_T;
        bf16* sKl = sKh + 64 * ASTR;
        bf16* sVh = sKl + 64 * ASTR;
        bf16* sVl = sVh + 64 * ASTR;
        const bf16* gKh = g_kh + kvbase + (size_t)t0 * HDIM;
        const bf16* gKl = g_kl + kvbase + (size_t)t0 * HDIM;
        for (int c = tid; c < 512; c += 256) {
            int r = c >> 3, co = (c & 7) * 8;
            cpasync16(gKh + r * 64 + co, sKh + r * ASTR + co);
            cpasync16(gKl + r * 64 + co, sKl + r * ASTR + co);
        }
        const bf16* gVh = g_vth + kvbase + t0;
        const bf16* gVl = g_vtl + kvbase + t0;
        for (int c = tid; c < 512; c += 256) {
            int r = c >> 3, co = (c & 7) * 8;
            cpasync16(gVh + r * 1024 + co, sVh + r * ASTR + co);
            cpasync16(gVl + r * 1024 + co, sVl + r * ASTR + co);
        }
        unsigned char* smk = smaskb + s * 8192;
        const unsigned char* gm = g_mask + (size_t)q0 * NTOK + t0;
        for (int c = tid; c < 512; c += 256) {
            int r = c >> 2, co = (c & 3) * 16;
            cpasync16(gm + (size_t)r * NTOK + co, smk + r * 64 + co);
        }
        asm volatile("cp.async.commit_group;" ::: "memory");
    };

    load_tile(0, 0);
    int bn = ((l >> 4) & 1) * 8 + (l & 7), bk = ((l >> 3) & 1) * 8;

    for (int t = 0; t < 16; t++) {
        if (t < 15) {
            load_tile((t + 1) & 1, (t + 1) * 64);
            asm volatile("cp.async.wait_group 1;" ::: "memory");
        } else {
            asm volatile("cp.async.wait_group 0;" ::: "memory");
        }
        __syncthreads();
        int s = t & 1;
        const bf16* sKh = sm + s * STG_T;
        const bf16* sKl = sKh + 64 * ASTR;
        const bf16* sVh = sKl + 64 * ASTR;
        const bf16* sVl = sVh + 64 * ASTR;
        const unsigned char* smk = smaskb + s * 8192;

        // ---- S = Q K^T (3-pass split) ----
        float s_acc[8][4];
#pragma unroll
        for (int j = 0; j < 8; j++)
#pragma unroll
            for (int v = 0; v < 4; v++) s_acc[j][v] = 0.f;
#pragma unroll
        for (int kt = 0; kt < 4; kt++)
#pragma unroll
            for (int jj = 0; jj < 4; jj++) {
                unsigned kb[4], kl2[4];
                ldm4(kb[0], kb[1], kb[2], kb[3],
                     sKh + (jj * 16 + bn) * ASTR + kt * 16 + bk);
                ldm4(kl2[0], kl2[1], kl2[2], kl2[3],
                     sKl + (jj * 16 + bn) * ASTR + kt * 16 + bk);
                mma16816(s_acc[2*jj],   qh[kt], kb);
                mma16816(s_acc[2*jj+1], qh[kt], kb + 2);
                mma16816(s_acc[2*jj],   qh[kt], kl2);
                mma16816(s_acc[2*jj+1], qh[kt], kl2 + 2);
                mma16816(s_acc[2*jj],   ql[kt], kb);
                mma16816(s_acc[2*jj+1], ql[kt], kb + 2);
            }

        // ---- softcap + exp(s-50) + mask, split+pack P ----
        unsigned pah[4][4], pal[4][4];
        int rbase = (wm + (l >> 2)) * 64;
#pragma unroll
        for (int j = 0; j < 8; j++) {
            bf16 hh[4], ll[4];
#pragma unroll
            for (int v = 0; v < 4; v++) {
                float sv = s_acc[j][v];            // already * hd^-0.5
                float x = sv * 0.02f;              // s / 50
                float t2;
                if (__builtin_expect(fabsf(x) < 0.25f, 1)) {
                    float x2 = x * x;
                    t2 = x * fmaf(x2, fmaf(x2, fmaf(x2, -0.05396825f, 0.13333333f),
                                           -0.33333333f), 1.0f);
                } else {
                    t2 = tanhf(x);
                }
                // p = exp(50*t2 - 50) = 2^(72.134752*(t2-1))
                float p = ex2a(fmaf(t2, 72.134752f, -72.134752f));
                int c = j * 8 + (l & 3) * 2 + (v & 1);
                int mi = rbase + ((v >= 2) ? 512 : 0) + c;
                p = smk[mi] ? p : 0.f;
                if (v < 2) ls0 += p; else ls1 += p;
                bf16 hb = __float2bfloat16(p);
                hh[v] = hb;
                ll[v] = __float2bfloat16(p - __bfloat162float(hb));
            }
            int kt = j >> 1, hf = (j & 1) * 2;
            pah[kt][hf + 0] = pack2(hh[0], hh[1]);
            pah[kt][hf + 1] = pack2(hh[2], hh[3]);
            pal[kt][hf + 0] = pack2(ll[0], ll[1]);
            pal[kt][hf + 1] = pack2(ll[2], ll[3]);
        }

        // ---- O += P V^T (3-pass split) ----
#pragma unroll
        for (int kt = 0; kt < 4; kt++)
#pragma unroll
            for (int jj = 0; jj < 4; jj++) {
                unsigned vb[4], vl2[4];
                ldm4(vb[0], vb[1], vb[2], vb[3],
                     sVh + (jj * 16 + bn) * ASTR + kt * 16 + bk);
                ldm4(vl2[0], vl2[1], vl2[2], vl2[3],
                     sVl + (jj * 16 + bn) * ASTR + kt * 16 + bk);
                mma16816(o_acc[2*jj],   pah[kt], vb);
                mma16816(o_acc[2*jj+1], pah[kt], vb + 2);
                mma16816(o_acc[2*jj],   pah[kt], vl2);
                mma16816(o_acc[2*jj+1], pah[kt], vl2 + 2);
                mma16816(o_acc[2*jj],   pal[kt], vb);
                mma16816(o_acc[2*jj+1], pal[kt], vb + 2);
            }
        __syncthreads();
    }

    // ---- normalize + write split output ----
    ls0 += __shfl_xor_sync(0xffffffffu, ls0, 1);
    ls0 += __shfl_xor_sync(0xffffffffu, ls0, 2);
    ls1 += __shfl_xor_sync(0xffffffffu, ls1, 1);
    ls1 += __shfl_xor_sync(0xffffffffu, ls1, 2);
    float inv0 = 1.f / ls0, inv1 = 1.f / ls1;

    int r0 = q0 + wm + (l >> 2);
#pragma unroll
    for (int j = 0; j < 8; j++) {
        int c = h * HDIM + j * 8 + (l & 3) * 2;
        {
            float v0 = o_acc[j][0] * inv0, v1 = o_acc[j][1] * inv0;
            __nv_bfloat162 oh2, ol2;
            splitf(v0, oh2.x, ol2.x); splitf(v1, oh2.y, ol2.y);
            size_t o = ((size_t)b * NTOK + r0) * EDIM + c;
            *(__nv_bfloat162*)(g_oh + o) = oh2;
            *(__nv_bfloat162*)(g_ol + o) = ol2;
        }
        {
            float v0 = o_acc[j][2] * inv1, v1 = o_acc[j][3] * inv1;
            __nv_bfloat162 oh2, ol2;
            splitf(v0, oh2.x, ol2.x); splitf(v1, oh2.y, ol2.y);
            size_t o = ((size_t)b * NTOK + r0 + 8) * EDIM + c;
            *(__nv_bfloat162*)(g_oh + o) = oh2;
            *(__nv_bfloat162*)(g_ol + o) = ol2;
        }
    }
}

// ----------------------------- output projection ----------------------------
__global__ __launch_bounds__(256) void k_out(float* __restrict__ out) {
    int m0 = blockIdx.y * 128, n0 = blockIdx.x * 128;
    float acc[2][8][4];
#pragma unroll
    for (int i = 0; i < 2; i++)
#pragma unroll
        for (int j = 0; j < 8; j++)
#pragma unroll
            for (int q = 0; q < 4; q++) acc[i][j][q] = 0.f;

    gemm_main3<128>(g_oh + (size_t)m0 * 1024, g_ol + (size_t)m0 * 1024, 1024,
                    g_wh + (size_t)3 * 1048576 + (size_t)n0 * 1024,
                    g_wl + (size_t)3 * 1048576 + (size_t)n0 * 1024, 1024,
                    1024, acc);

    int l = threadIdx.x & 31, wid = threadIdx.x >> 5;
    int wm = (wid & 3) * 32, wn = (wid >> 2) * 64;
#pragma unroll
    for (int i = 0; i < 2; i++)
#pragma unroll
        for (int j = 0; j < 8; j++) {
            int r = m0 + wm + i * 16 + (l >> 2);
            int c = n0 + wn + j * 8 + (l & 3) * 2;
#pragma unroll
            for (int h2 = 0; h2 < 2; h2++) {
                int rr = r + h2 * 8;
                out[(size_t)rr * EDIM + c]     = acc[i][j][h2 * 2 + 0];
                out[(size_t)rr * EDIM + c + 1] = acc[i][j][h2 * 2 + 1];
            }
        }
}

// ----------------------------------------------------------------------------
extern "C" void kernel_launch(void* const* d_in, const int* in_sizes, int n_in,
                              void* d_out, int out_size) {
    const float* x    = (const float*)d_in[0];
    const float* Wq   = (const float*)d_in[1];
    const float* Wk   = (const float*)d_in[2];
    const float* Wv   = (const float*)d_in[3];
    const float* Wo   = (const float*)d_in[4];
    const float* qg   = (const float*)d_in[5];
    const float* kgm  = (const float*)d_in[6];
    const float* cosb = (const float*)d_in[7];
    const float* sinb = (const float*)d_in[8];
    const int*   ridx = (const int*)d_in[9];
    const void*  mraw = (const void*)d_in[10];
    float* out = (float*)d_out;

    cudaFuncSetAttribute(k_gemm_qkv, cudaFuncAttributeMaxDynamicSharedMemorySize, 81920);
    cudaFuncSetAttribute(k_out,      cudaFuncAttributeMaxDynamicSharedMemorySize, 81920);
    cudaFuncSetAttribute(k_attn,     cudaFuncAttributeMaxDynamicSharedMemorySize, 90112);

    mask_detect_kernel<<<1, 1024>>>((const unsigned int*)mraw);
    mask_convert_kernel<<<4096, 256>>>(mraw);

    k_split_x<<<8192, 256>>>(x);
    k_split_w<<<1024, 256>>>(Wq, 0);
    k_split_w<<<1024, 256>>>(Wk, 1);
    k_split_w<<<1024, 256>>>(Wv, 2);
    k_split_w<<<1024, 256>>>(Wo, 3);

    k_gemm_qkv<<<dim3(8, 64, 3), 256, 81920>>>();

    norm_rope_kernel<<<(2 * BHN) / 8, 256>>>(qg, kgm, cosb, sinb, ridx);

    k_attn<<<dim3(8, BH), 256, 90112>>>();

    k_out<<<dim3(8, 64), 256, 81920>>>(out);
}